// round 13
// baseline (speedup 1.0000x reference)
#include <cuda_runtime.h>

// FiniteDifference: x [B=4, T=16, H=128, W=128, C=16] fp32
// out = concat(dy (d/dH), dx (d/dW), dz (d/dT)); central diff, zero pad.
//
// FINAL — roofline kernel, converged after 12 rounds / 9 structural variants.
//
// Model (validated): pure write-drain workload. DRAM traffic == ~201 MB
// compulsory write stream; the 64 MiB input stays L2-resident so reads are
// ~free. Write-drain throughput plateaus at ~5.3 TB/s, independent of store
// width (.128/.256), store path (STG/__stcs/TMA bulk), stream mix (fused vs
// axis-split), block shape (128-512), wave structure (flat vs persistent),
// and occupancy (40-93%). Kernel time 39.9 us ~= 96% of the 38 us floor.
//
// Rejected (measured): 2x MLP/thread +31% (occupancy cliff), axis-split
// CTAs +52% (breaks L2 reuse: +70% DRAM traffic), v8 ld/st +3%, TMA bulk
// stores +4%, block=512 +1.5%, persistent grid-stride +33%, store
// reordering neutral, __stcs neutral (kept: protects L2 residency at
// zero cost).

#define N4_TOTAL (4 * 16 * 128 * 128 * 4)  // 4,194,304 float4 elems per output

__device__ __forceinline__ float4 sub4(float4 a, float4 b) {
    return make_float4(a.x - b.x, a.y - b.y, a.z - b.z, a.w - b.w);
}

__global__ void __launch_bounds__(256)
fd_kernel(const float4* __restrict__ x, float4* __restrict__ out)
{
    int i = blockIdx.x * blockDim.x + threadIdx.x;

    int w = (i >> 2)  & 127;
    int h = (i >> 9)  & 127;
    int t = (i >> 16) & 15;

    const float4 zero = make_float4(0.f, 0.f, 0.f, 0.f);

    float4 hp = (h < 127) ? x[i + 512]   : zero;
    float4 hm = (h > 0)   ? x[i - 512]   : zero;
    float4 wp = (w < 127) ? x[i + 4]     : zero;
    float4 wm = (w > 0)   ? x[i - 4]     : zero;
    float4 tp = (t < 15)  ? x[i + 65536] : zero;
    float4 tm = (t > 0)   ? x[i - 65536] : zero;

    __stcs(&out[i],                sub4(hp, hm));  // dy
    __stcs(&out[i + N4_TOTAL],     sub4(wp, wm));  // dx
    __stcs(&out[i + 2 * N4_TOTAL], sub4(tp, tm));  // dz
}

extern "C" void kernel_launch(void* const* d_in, const int* in_sizes, int n_in,
                              void* d_out, int out_size)
{
    const float4* x = (const float4*)d_in[0];
    float4* out = (float4*)d_out;

    fd_kernel<<<N4_TOTAL / 256, 256>>>(x, out);
}